// round 6
// baseline (speedup 1.0000x reference)
#include <cuda_runtime.h>
#include <cuda_fp16.h>

#define BB 2
#define NN 512
#define FF 64
#define CC 256
#define LN_EPS 1e-6f
#define GRID_MAIN 148

// ---------------- device scratch (static, no allocation) ----------------
__device__ float  d_Aq[BB * NN * CC];            // qs @ Wa1[0:64] + ba1
__device__ float  d_Ak[BB * NN * CC];            // ks @ Wa1[64:128]
__device__ float  d_vproj[BB * NN * FF];         // vs @ Wv + bv
__device__ __align__(16) __half d_Wa2t[CC * CC]; // Wa2 transposed [n][k], fp16
__device__ float  d_pool[BB * FF];               // max-pool accumulator

// ---------------- helpers ----------------
__device__ __forceinline__ float gelu_f(float x) {
    // jax.nn.gelu (approximate): 0.5x(1+tanh(0.79788456(x+0.044715x^3)))
    float z = 0.7978845608028654f * x * fmaf(0.044715f, x * x, 1.0f);
    float t;
    asm("tanh.approx.f32 %0, %1;" : "=f"(t) : "f"(z));
    float hx = 0.5f * x;
    return fmaf(hx, t, hx);
}

__device__ __forceinline__ void mma16816(float d[4], const unsigned a[4], const unsigned b0, const unsigned b1) {
    asm volatile(
        "mma.sync.aligned.m16n8k16.row.col.f32.f16.f16.f32 "
        "{%0,%1,%2,%3}, {%4,%5,%6,%7}, {%8,%9}, {%0,%1,%2,%3};\n"
        : "+f"(d[0]), "+f"(d[1]), "+f"(d[2]), "+f"(d[3])
        : "r"(a[0]), "r"(a[1]), "r"(a[2]), "r"(a[3]), "r"(b0), "r"(b1));
}

__device__ __forceinline__ void ldsm_x4(unsigned r[4], const __half* p) {
    unsigned addr = (unsigned)__cvta_generic_to_shared(p);
    asm volatile("ldmatrix.sync.aligned.m8n8.x4.shared.b16 {%0,%1,%2,%3}, [%4];"
                 : "=r"(r[0]), "=r"(r[1]), "=r"(r[2]), "=r"(r[3]) : "r"(addr));
}

__device__ __forceinline__ void atomicMaxF(float* addr, float v) {
    if (v >= 0.f) atomicMax((int*)addr, __float_as_int(v));
    else          atomicMin((unsigned int*)addr, __float_as_uint(v));
}

// ---------------- prep: Aq/Ak/vproj + Wa2 transpose-to-half + pool init ----------------
__global__ void k_prep(const float* __restrict__ qs, const float* __restrict__ ks,
                       const float* __restrict__ vs, const float* __restrict__ Wa1,
                       const float* __restrict__ ba1, const float* __restrict__ Wv,
                       const float* __restrict__ bv, const float* __restrict__ Wa2) {
    int tid = threadIdx.x;
    if (blockIdx.x < BB * NN) {
        __shared__ float sq[FF], sk[FF], sv[FF];
        int row = blockIdx.x;
        if (tid < FF) {
            sq[tid] = qs[row * FF + tid];
            sk[tid] = ks[row * FF + tid];
            sv[tid] = vs[row * FF + tid];
        }
        __syncthreads();
        float aq = ba1[tid], ak = 0.f;
#pragma unroll 8
        for (int f = 0; f < FF; ++f) {
            aq += sq[f] * Wa1[f * CC + tid];
            ak += sk[f] * Wa1[(FF + f) * CC + tid];
        }
        d_Aq[row * CC + tid] = aq;
        d_Ak[row * CC + tid] = ak;
        if (tid < FF) {
            float vp = bv[tid];
#pragma unroll 8
            for (int f = 0; f < FF; ++f) vp += sv[f] * Wv[f * FF + tid];
            d_vproj[row * FF + tid] = vp;
        }
    } else {
        int blk = blockIdx.x - BB * NN;      // 0..63
        for (int idx = blk * 256 + tid; idx < CC * CC; idx += 64 * 256) {
            int kk = idx >> 8, n = idx & 255;
            d_Wa2t[n * CC + kk] = __float2half(Wa2[idx]);
        }
        if (blk == 0 && tid < BB * FF) d_pool[tid] = __int_as_float(0xff800000); // -inf
    }
}

// ---------------- fill: rows with q >= vlen get ctx = LN(0) = ln1_b ----------------
__global__ void k_fill(const int* __restrict__ valid_lens,
                       const float* __restrict__ ln1_b, float* __restrict__ out) {
    int row = blockIdx.x;                   // 0..BB*NN-1
    int b = row >> 9, q = row & 511;
    if (q >= valid_lens[b]) out[row * FF + threadIdx.x] = ln1_b[threadIdx.x];
}

// ---------------- main fused kernel: persistent, 512 threads ----------------
#define PITCH 264
#define SMEM_BYTES ((256 + 128) * PITCH * 2 + 3778 * 4)

__global__ void __launch_bounds__(512, 1)
k_main(const float* __restrict__ qs_s, const float* __restrict__ ks_s,
       const float* __restrict__ qs_t, const float* __restrict__ ks_t,
       const int* __restrict__ valid_lens,
       const float* __restrict__ Wa1, const float* __restrict__ ba2,
       const float* __restrict__ Wa3, const float* __restrict__ ba3,
       const float* __restrict__ ln1_s, const float* __restrict__ ln1_b,
       const float* __restrict__ Wg1, const float* __restrict__ bg1,
       const float* __restrict__ Wg2, const float* __restrict__ bg2,
       float* __restrict__ out) {
    extern __shared__ char smem_raw[];
    __half* sWb = (__half*)smem_raw;        // [256][PITCH]  Wa2^T padded
    __half* sH  = sWb + 256 * PITCH;        // [128][PITCH]  h1 tile (fp16)
    float* fbse   = (float*)(sH + 128 * PITCH);
    float* sAq    = fbse;                   // 256
    float* sWe    = sAq + 256;              // 5*256 (Wa1 rows 128..132)
    float* sBa2   = sWe + 1280;             // 256
    float* sWa3   = sBa2 + 256;             // 256
    float* sE     = sWa3 + 256;             // [128][6]: dx,dy,dist,dist2,tdiff,mask
    float* sAttn  = sE + 768;               // 128
    float* sCtxAcc= sAttn + 128;            // [8][64]
    float* sCtxRow= sCtxAcc + 512;          // 64
    float* sHg    = sCtxRow + 64;           // 256
    float* sRed   = sHg + 256;              // 2

    const int tid = threadIdx.x;

    // ---- per-CTA constants, loaded ONCE (persistent CTA) ----
    {
        const uint4* src = (const uint4*)d_Wa2t;
        for (int i = tid; i < 256 * 32; i += 512) {
            int n = i >> 5, j = i & 31;
            *(uint4*)(sWb + n * PITCH + j * 8) = src[i];
        }
    }
    if (tid < 256) {
        sBa2[tid] = ba2[tid];
        sWa3[tid] = Wa3[tid];
    }
    for (int i = tid; i < 5 * 256; i += 512) sWe[i] = Wa1[128 * CC + i];
    const float ba3v = ba3[0];
    const int vlen0 = valid_lens[0];
    const int vlen1 = valid_lens[1];
    const int total = vlen0 + vlen1;

    const int lane = tid & 31, warp = tid >> 5;
    const int g = lane >> 2, tig = lane & 3;
    const int wm = warp >> 2, wn = warp & 3;     // 4x4 warp grid
    const int m_base = wm * 32;                  // M: 32 rows per warp
    const int n_base = wn * 64;                  // N: 64 cols per warp
    const int lrow = lane & 15;
    const int lcol = (lane >> 4) << 3;

    for (int w = blockIdx.x; w < total; w += GRID_MAIN) {
        const int b = (w >= vlen0) ? 1 : 0;
        const int q = b ? (w - vlen0) : w;
        const int rowq = b * NN + q;

        // per-row prologue
        if (tid < 256) sAq[tid] = d_Aq[rowq * CC + tid];
        sCtxAcc[tid] = 0.f;
        const float qsx = qs_s[rowq * 2 + 0], qsy = qs_s[rowq * 2 + 1];
        const float qt  = qs_t[rowq];
        __syncthreads();

        for (int chunk = 0; chunk < 4; ++chunk) {
            const int k0 = chunk * 128;
            // --- pair features + mask (mask = t_diff > 0; q < vlen guaranteed) ---
            if (tid < 128) {
                int krow = b * NN + k0 + tid;
                float dx = qsx - ks_s[krow * 2 + 0];
                float dy = qsy - ks_s[krow * 2 + 1];
                float dist = sqrtf(dx * dx + dy * dy);
                float td = qt - ks_t[krow];
                sE[tid * 6 + 0] = dx;  sE[tid * 6 + 1] = dy;
                sE[tid * 6 + 2] = dist; sE[tid * 6 + 3] = dist * dist;
                sE[tid * 6 + 4] = td;
                sE[tid * 6 + 5] = (td > 0.f) ? 1.f : 0.f;
                sAttn[tid] = 0.f;
            }
            __syncthreads();
            // --- h1 = gelu(Aq + Ak + extras @ Wa1_e), fp16 into SMEM ---
            for (int idx = tid; idx < 128 * 128; idx += 512) {
                int m = idx >> 7;
                int cp = idx & 127;
                int c = cp * 2;
                float2 ak = ((const float2*)(d_Ak + (b * NN + k0 + m) * CC))[cp];
                float e0 = sE[m * 6], e1 = sE[m * 6 + 1], e2 = sE[m * 6 + 2];
                float e3 = sE[m * 6 + 3], e4 = sE[m * 6 + 4];
                float p0 = sAq[c]     + ak.x + e0 * sWe[c]     + e1 * sWe[256 + c]
                         + e2 * sWe[512 + c]     + e3 * sWe[768 + c]     + e4 * sWe[1024 + c];
                float p1 = sAq[c + 1] + ak.y + e0 * sWe[c + 1] + e1 * sWe[257 + c]
                         + e2 * sWe[513 + c]     + e3 * sWe[769 + c]     + e4 * sWe[1025 + c];
                *(__half2*)(sH + m * PITCH + c) = __floats2half2_rn(gelu_f(p0), gelu_f(p1));
            }
            __syncthreads();
            // --- GEMM2 (128x256x256, fp16 mma + ldmatrix) fused gelu + dot(Wa3) ---
            {
                float acc[2][8][4];
#pragma unroll
                for (int mt = 0; mt < 2; ++mt)
#pragma unroll
                    for (int nt = 0; nt < 8; ++nt)
#pragma unroll
                        for (int r = 0; r < 4; ++r) acc[mt][nt][r] = 0.f;

                const __half* pa0 = sH  + (m_base + lrow) * PITCH + lcol;
                const __half* pb0 = sWb + (n_base + lrow) * PITCH + lcol;
#pragma unroll 2
                for (int kk = 0; kk < 256; kk += 16) {
                    unsigned afr[2][4];
                    ldsm_x4(afr[0], pa0 + kk);
                    ldsm_x4(afr[1], pa0 + 16 * PITCH + kk);
#pragma unroll
                    for (int nb = 0; nb < 4; ++nb) {
                        unsigned bfr[4];
                        ldsm_x4(bfr, pb0 + nb * 16 * PITCH + kk);
#pragma unroll
                        for (int mt = 0; mt < 2; ++mt) {
                            mma16816(acc[mt][nb * 2 + 0], afr[mt], bfr[0], bfr[2]);
                            mma16816(acc[mt][nb * 2 + 1], afr[mt], bfr[1], bfr[3]);
                        }
                    }
                }
                // epilogue: h2 = gelu(acc + ba2); partial attn = h2 . Wa3
                float p[4] = {0.f, 0.f, 0.f, 0.f};
#pragma unroll
                for (int nt = 0; nt < 8; ++nt) {
                    int col = n_base + nt * 8 + 2 * tig;
                    float bb0 = sBa2[col], bb1 = sBa2[col + 1];
                    float w0 = sWa3[col], w1 = sWa3[col + 1];
#pragma unroll
                    for (int mt = 0; mt < 2; ++mt) {
                        p[mt * 2 + 0] += gelu_f(acc[mt][nt][0] + bb0) * w0
                                       + gelu_f(acc[mt][nt][1] + bb1) * w1;
                        p[mt * 2 + 1] += gelu_f(acc[mt][nt][2] + bb0) * w0
                                       + gelu_f(acc[mt][nt][3] + bb1) * w1;
                    }
                }
#pragma unroll
                for (int off = 1; off < 4; off <<= 1) {
                    p[0] += __shfl_xor_sync(0xffffffffu, p[0], off);
                    p[1] += __shfl_xor_sync(0xffffffffu, p[1], off);
                    p[2] += __shfl_xor_sync(0xffffffffu, p[2], off);
                    p[3] += __shfl_xor_sync(0xffffffffu, p[3], off);
                }
                if (tig == 0) {
                    atomicAdd(&sAttn[m_base + g],      p[0]);
                    atomicAdd(&sAttn[m_base + g + 8],  p[1]);
                    atomicAdd(&sAttn[m_base + g + 16], p[2]);
                    atomicAdd(&sAttn[m_base + g + 24], p[3]);
                }
            }
            __syncthreads();
            // --- mask + ba3 ---
            if (tid < 128) {
                float a = sAttn[tid] + ba3v;
                sAttn[tid] = sE[tid * 6 + 5] * a;
            }
            __syncthreads();
            // --- ctx += attn . vproj ---
            {
                int d = tid & 63, grp = tid >> 6;          // grp 0..7, 16 rows each
                float partial = 0.f;
                const float* vp = d_vproj + (b * NN + k0 + grp * 16) * FF + d;
#pragma unroll 8
                for (int m = 0; m < 16; ++m) partial += sAttn[grp * 16 + m] * vp[m * FF];
                sCtxAcc[grp * 64 + d] += partial;
            }
            __syncthreads();
        }

        // --- reduce + LayerNorm1 ---
        if (tid < 64) {
            float s = 0.f;
#pragma unroll
            for (int gg = 0; gg < 8; ++gg) s += sCtxAcc[gg * 64 + tid];
            sCtxRow[tid] = s;
        }
        __syncthreads();
        if (tid < 32) {
            float s = sCtxRow[tid] + sCtxRow[tid + 32];
#pragma unroll
            for (int off = 16; off > 0; off >>= 1) s += __shfl_xor_sync(0xffffffffu, s, off);
            if (tid == 0) sRed[0] = s * (1.f / 64.f);
        }
        __syncthreads();
        if (tid < 32) {
            float mu = sRed[0];
            float d0 = sCtxRow[tid] - mu, d1 = sCtxRow[tid + 32] - mu;
            float s = d0 * d0 + d1 * d1;
#pragma unroll
            for (int off = 16; off > 0; off >>= 1) s += __shfl_xor_sync(0xffffffffu, s, off);
            if (tid == 0) sRed[1] = rsqrtf(s * (1.f / 64.f) + LN_EPS);
        }
        __syncthreads();
        if (tid < 64) {
            float mu = sRed[0], rs = sRed[1];
            float o = (sCtxRow[tid] - mu) * rs * ln1_s[tid] + ln1_b[tid];
            out[rowq * FF + tid] = o;
            sCtxRow[tid] = o;
        }
        __syncthreads();
        // --- gate MLP + masked max-pool (q < vlen guaranteed) ---
        if (tid < 256) {
            float hg = bg1[tid];
#pragma unroll 8
            for (int f = 0; f < FF; ++f) hg += sCtxRow[f] * Wg1[f * CC + tid];
            sHg[tid] = gelu_f(hg);
        }
        __syncthreads();
        if (tid < 64) {
            float gsum = bg2[tid];
#pragma unroll 8
            for (int c2 = 0; c2 < CC; ++c2) gsum += sHg[c2] * Wg2[c2 * FF + tid];
            float val = gsum * sCtxRow[tid];
            atomicMaxF(&d_pool[b * FF + tid], val);
        }
        __syncthreads();
    }
}

// ---------------- vnode: LN2 over pooled ----------------
__global__ void k_vnode(const float* __restrict__ ln2_s, const float* __restrict__ ln2_b,
                        float* __restrict__ out) {
    int t = threadIdx.x;           // 0..127
    int b = t >> 6, d = t & 63;
    __shared__ float sp[128], sMu[2], sRs[2];
    float x = d_pool[t];
    sp[t] = x;
    __syncthreads();
    if (t < 2) {
        float mu = 0.f;
        for (int i = 0; i < 64; ++i) mu += sp[t * 64 + i];
        mu *= (1.f / 64.f);
        float v = 0.f;
        for (int i = 0; i < 64; ++i) { float dd = sp[t * 64 + i] - mu; v += dd * dd; }
        v *= (1.f / 64.f);
        sMu[t] = mu;
        sRs[t] = rsqrtf(v + LN_EPS);
    }
    __syncthreads();
    out[BB * NN * FF + t] = (x - sMu[b]) * sRs[b] * ln2_s[d] + ln2_b[d];
}

// ---------------- launch ----------------
extern "C" void kernel_launch(void* const* d_in, const int* in_sizes, int n_in,
                              void* d_out, int out_size) {
    (void)in_sizes; (void)n_in; (void)out_size;
    const float* qs    = (const float*)d_in[0];
    const float* ks    = (const float*)d_in[1];
    const float* vs    = (const float*)d_in[2];
    const float* qs_s  = (const float*)d_in[3];
    const float* ks_s  = (const float*)d_in[4];
    const float* qs_t  = (const float*)d_in[5];
    const float* ks_t  = (const float*)d_in[6];
    const int*   vl    = (const int*)d_in[7];
    const float* Wv    = (const float*)d_in[8];
    const float* bv    = (const float*)d_in[9];
    const float* Wa1   = (const float*)d_in[10];
    const float* ba1   = (const float*)d_in[11];
    const float* Wa2   = (const float*)d_in[12];
    const float* ba2   = (const float*)d_in[13];
    const float* Wa3   = (const float*)d_in[14];
    const float* ba3   = (const float*)d_in[15];
    const float* Wg1   = (const float*)d_in[16];
    const float* bg1   = (const float*)d_in[17];
    const float* Wg2   = (const float*)d_in[18];
    const float* bg2   = (const float*)d_in[19];
    const float* ln1_s = (const float*)d_in[20];
    const float* ln1_b = (const float*)d_in[21];
    const float* ln2_s = (const float*)d_in[22];
    const float* ln2_b = (const float*)d_in[23];
    float* out = (float*)d_out;

    cudaFuncSetAttribute(k_main, cudaFuncAttributeMaxDynamicSharedMemorySize, SMEM_BYTES);

    k_prep<<<BB * NN + 64, 256>>>(qs, ks, vs, Wa1, ba1, Wv, bv, Wa2);
    k_fill<<<BB * NN, FF>>>(vl, ln1_b, out);
    k_main<<<GRID_MAIN, 512, SMEM_BYTES>>>(qs_s, ks_s, qs_t, ks_t, vl,
                                           Wa1, ba2, Wa3, ba3, ln1_s, ln1_b,
                                           Wg1, bg1, Wg2, bg2, out);
    k_vnode<<<1, 128>>>(ln2_s, ln2_b, out);
}

// round 7
// speedup vs baseline: 1.4718x; 1.4718x over previous
#include <cuda_runtime.h>
#include <cuda_fp16.h>

#define BB 2
#define NN 512
#define FF 64
#define CC 256
#define LN_EPS 1e-6f

// ---------------- device scratch (static, no allocation) ----------------
__device__ float  d_Aq[BB * NN * CC];            // qs @ Wa1[0:64] + ba1
__device__ float  d_Ak[BB * NN * CC];            // ks @ Wa1[64:128]
__device__ float  d_vproj[BB * NN * FF];         // vs @ Wv + bv
__device__ __align__(16) __half d_Wa2t[CC * CC]; // Wa2 transposed [n][k], fp16
__device__ float  d_pool[BB * FF];               // max-pool accumulator

// ---------------- helpers ----------------
__device__ __forceinline__ float gelu_f(float x) {
    // jax.nn.gelu (approximate): 0.5x(1+tanh(0.79788456(x+0.044715x^3)))
    float z = 0.7978845608028654f * x * fmaf(0.044715f, x * x, 1.0f);
    float t;
    asm("tanh.approx.f32 %0, %1;" : "=f"(t) : "f"(z));
    float hx = 0.5f * x;
    return fmaf(hx, t, hx);
}

__device__ __forceinline__ void mma16816(float d[4], const unsigned a[4], const unsigned b0, const unsigned b1) {
    asm volatile(
        "mma.sync.aligned.m16n8k16.row.col.f32.f16.f16.f32 "
        "{%0,%1,%2,%3}, {%4,%5,%6,%7}, {%8,%9}, {%0,%1,%2,%3};\n"
        : "+f"(d[0]), "+f"(d[1]), "+f"(d[2]), "+f"(d[3])
        : "r"(a[0]), "r"(a[1]), "r"(a[2]), "r"(a[3]), "r"(b0), "r"(b1));
}

__device__ __forceinline__ void ldsm_x4(unsigned r[4], const __half* p) {
    unsigned addr = (unsigned)__cvta_generic_to_shared(p);
    asm volatile("ldmatrix.sync.aligned.m8n8.x4.shared.b16 {%0,%1,%2,%3}, [%4];"
                 : "=r"(r[0]), "=r"(r[1]), "=r"(r[2]), "=r"(r[3]) : "r"(addr));
}

__device__ __forceinline__ void atomicMaxF(float* addr, float v) {
    if (v >= 0.f) atomicMax((int*)addr, __float_as_int(v));
    else          atomicMin((unsigned int*)addr, __float_as_uint(v));
}

// ---------------- prep: Aq/Ak/vproj + Wa2 transpose-to-half + pool init ----------------
__global__ void k_prep(const float* __restrict__ qs, const float* __restrict__ ks,
                       const float* __restrict__ vs, const float* __restrict__ Wa1,
                       const float* __restrict__ ba1, const float* __restrict__ Wv,
                       const float* __restrict__ bv, const float* __restrict__ Wa2) {
    int tid = threadIdx.x;
    if (blockIdx.x < BB * NN) {
        __shared__ float sq[FF], sk[FF], sv[FF];
        int row = blockIdx.x;
        if (tid < FF) {
            sq[tid] = qs[row * FF + tid];
            sk[tid] = ks[row * FF + tid];
            sv[tid] = vs[row * FF + tid];
        }
        __syncthreads();
        float aq = ba1[tid], ak = 0.f;
#pragma unroll 8
        for (int f = 0; f < FF; ++f) {
            aq += sq[f] * Wa1[f * CC + tid];
            ak += sk[f] * Wa1[(FF + f) * CC + tid];
        }
        d_Aq[row * CC + tid] = aq;
        d_Ak[row * CC + tid] = ak;
        if (tid < FF) {
            float vp = bv[tid];
#pragma unroll 8
            for (int f = 0; f < FF; ++f) vp += sv[f] * Wv[f * FF + tid];
            d_vproj[row * FF + tid] = vp;
        }
    } else {
        int blk = blockIdx.x - BB * NN;      // 0..63
        for (int idx = blk * 256 + tid; idx < CC * CC; idx += 64 * 256) {
            int kk = idx >> 8, n = idx & 255;
            d_Wa2t[n * CC + kk] = __float2half(Wa2[idx]);
        }
        if (blk == 0 && tid < BB * FF) d_pool[tid] = __int_as_float(0xff800000); // -inf
    }
}

// ---------------- main fused kernel: one CTA per (b, q), 512 threads ----------------
#define PITCH 264
#define SMEM_BYTES ((256 + 128) * PITCH * 2 + 3778 * 4)

__global__ void __launch_bounds__(512, 1)
k_main(const float* __restrict__ qs_s, const float* __restrict__ ks_s,
       const float* __restrict__ qs_t, const float* __restrict__ ks_t,
       const int* __restrict__ valid_lens,
       const float* __restrict__ Wa1, const float* __restrict__ ba2,
       const float* __restrict__ Wa3, const float* __restrict__ ba3,
       const float* __restrict__ ln1_s, const float* __restrict__ ln1_b,
       const float* __restrict__ Wg1, const float* __restrict__ bg1,
       const float* __restrict__ Wg2, const float* __restrict__ bg2,
       float* __restrict__ out) {
    extern __shared__ char smem_raw[];
    __half* sWb = (__half*)smem_raw;        // [256][PITCH]  Wa2^T padded
    __half* sH  = sWb + 256 * PITCH;        // [128][PITCH]  h1 tile (fp16)
    float* fbse   = (float*)(sH + 128 * PITCH);
    float* sAq    = fbse;                   // 256
    float* sWe    = sAq + 256;              // 5*256 (Wa1 rows 128..132)
    float* sBa2   = sWe + 1280;             // 256
    float* sWa3   = sBa2 + 256;             // 256
    float* sE     = sWa3 + 256;             // [128][6]: dx,dy,dist,dist2,tdiff,mask
    float* sAttn  = sE + 768;               // 128
    float* sCtxAcc= sAttn + 128;            // [8][64]
    float* sCtxRow= sCtxAcc + 512;          // 64
    float* sHg    = sCtxRow + 64;           // 256
    float* sRed   = sHg + 256;              // 2

    const int tid  = threadIdx.x;
    const int b    = blockIdx.x >> 9;
    const int q    = blockIdx.x & 511;
    const int rowq = b * NN + q;

    const int vlen = valid_lens[b];
    // mask = (q < vlen) && (t_diff > 0): validity applies to the QUERY axis.
    // For q >= vlen: attn row is all-zero -> ctx = LN(0) = ln1_b; pooled max
    // excludes this q. Skip all heavy work.
    if (q >= vlen) {
        if (tid < FF) out[rowq * FF + tid] = ln1_b[tid];
        return;
    }

    // Wa2^T -> SMEM with pad (row pitch 264 halves -> conflict-free LDSM)
    {
        const uint4* src = (const uint4*)d_Wa2t;
        for (int i = tid; i < 256 * 32; i += 512) {
            int n = i >> 5, j = i & 31;
            *(uint4*)(sWb + n * PITCH + j * 8) = src[i];
        }
    }
    if (tid < 256) {
        sAq[tid]  = d_Aq[rowq * CC + tid];
        sBa2[tid] = ba2[tid];
        sWa3[tid] = Wa3[tid];
    }
    for (int i = tid; i < 5 * 256; i += 512) sWe[i] = Wa1[128 * CC + i];
    sCtxAcc[tid] = 0.f;
    const float qsx = qs_s[rowq * 2 + 0], qsy = qs_s[rowq * 2 + 1];
    const float qt  = qs_t[rowq];
    const float ba3v = ba3[0];
    __syncthreads();

    const int lane = tid & 31, warp = tid >> 5;
    const int g = lane >> 2, tig = lane & 3;
    const int wm = warp >> 2, wn = warp & 3;     // 4x4 warp grid
    const int m_base = wm * 32;                  // M: 32 rows per warp
    const int n_base = wn * 64;                  // N: 64 cols per warp
    const int lrow = lane & 15;
    const int lcol = (lane >> 4) << 3;

    // h1-phase invariants: column is FIXED per thread -> hoist coefficient
    // loads out of the per-chunk loop entirely (registers, loaded once).
    const int h1_cp = tid & 127;
    const int h1_c  = h1_cp * 2;
    const int h1_m0 = tid >> 7;                  // 0..3
    const float aq0 = sAq[h1_c], aq1 = sAq[h1_c + 1];
    const float w00 = sWe[h1_c],        w01 = sWe[h1_c + 1];
    const float w10 = sWe[256 + h1_c],  w11 = sWe[257 + h1_c];
    const float w20 = sWe[512 + h1_c],  w21 = sWe[513 + h1_c];
    const float w30 = sWe[768 + h1_c],  w31 = sWe[769 + h1_c];
    const float w40 = sWe[1024 + h1_c], w41 = sWe[1025 + h1_c];

    for (int chunk = 0; chunk < 4; ++chunk) {
        const int k0 = chunk * 128;
        // --- pair features + mask (q < vlen guaranteed) ---
        if (tid < 128) {
            int krow = b * NN + k0 + tid;
            float dx = qsx - ks_s[krow * 2 + 0];
            float dy = qsy - ks_s[krow * 2 + 1];
            float dist = sqrtf(dx * dx + dy * dy);
            float td = qt - ks_t[krow];
            sE[tid * 6 + 0] = dx;  sE[tid * 6 + 1] = dy;
            sE[tid * 6 + 2] = dist; sE[tid * 6 + 3] = dist * dist;
            sE[tid * 6 + 4] = td;
            sE[tid * 6 + 5] = (td > 0.f) ? 1.f : 0.f;
            sAttn[tid] = 0.f;
        }
        __syncthreads();
        // --- h1 = gelu(Aq + Ak + extras @ Wa1_e), fp16 into SMEM ---
        {
            const float2* akp = (const float2*)(d_Ak + (b * NN + k0 + h1_m0) * CC) + h1_cp;
#pragma unroll 4
            for (int it = 0; it < 32; ++it) {
                const int m = h1_m0 + it * 4;
                float2 ak = akp[it * 4 * (CC / 2)];
                float e0 = sE[m * 6], e1 = sE[m * 6 + 1], e2 = sE[m * 6 + 2];
                float e3 = sE[m * 6 + 3], e4 = sE[m * 6 + 4];
                float p0 = aq0 + ak.x + e0 * w00 + e1 * w10 + e2 * w20 + e3 * w30 + e4 * w40;
                float p1 = aq1 + ak.y + e0 * w01 + e1 * w11 + e2 * w21 + e3 * w31 + e4 * w41;
                *(__half2*)(sH + m * PITCH + h1_c) = __floats2half2_rn(gelu_f(p0), gelu_f(p1));
            }
        }
        __syncthreads();
        // --- GEMM2 (128x256x256, fp16 mma + ldmatrix) fused gelu + dot(Wa3) ---
        {
            float acc[2][8][4];
#pragma unroll
            for (int mt = 0; mt < 2; ++mt)
#pragma unroll
                for (int nt = 0; nt < 8; ++nt)
#pragma unroll
                    for (int r = 0; r < 4; ++r) acc[mt][nt][r] = 0.f;

            const __half* pa0 = sH  + (m_base + lrow) * PITCH + lcol;
            const __half* pb0 = sWb + (n_base + lrow) * PITCH + lcol;
#pragma unroll 2
            for (int kk = 0; kk < 256; kk += 16) {
                unsigned afr[2][4];
                ldsm_x4(afr[0], pa0 + kk);
                ldsm_x4(afr[1], pa0 + 16 * PITCH + kk);
#pragma unroll
                for (int nb = 0; nb < 4; ++nb) {
                    unsigned bfr[4];
                    ldsm_x4(bfr, pb0 + nb * 16 * PITCH + kk);
#pragma unroll
                    for (int mt = 0; mt < 2; ++mt) {
                        mma16816(acc[mt][nb * 2 + 0], afr[mt], bfr[0], bfr[2]);
                        mma16816(acc[mt][nb * 2 + 1], afr[mt], bfr[1], bfr[3]);
                    }
                }
            }
            // epilogue: h2 = gelu(acc + ba2); partial attn = h2 . Wa3
            float p[4] = {0.f, 0.f, 0.f, 0.f};
#pragma unroll
            for (int nt = 0; nt < 8; ++nt) {
                int col = n_base + nt * 8 + 2 * tig;
                float bb0 = sBa2[col], bb1 = sBa2[col + 1];
                float w0 = sWa3[col], w1 = sWa3[col + 1];
#pragma unroll
                for (int mt = 0; mt < 2; ++mt) {
                    p[mt * 2 + 0] += gelu_f(acc[mt][nt][0] + bb0) * w0
                                   + gelu_f(acc[mt][nt][1] + bb1) * w1;
                    p[mt * 2 + 1] += gelu_f(acc[mt][nt][2] + bb0) * w0
                                   + gelu_f(acc[mt][nt][3] + bb1) * w1;
                }
            }
#pragma unroll
            for (int off = 1; off < 4; off <<= 1) {
                p[0] += __shfl_xor_sync(0xffffffffu, p[0], off);
                p[1] += __shfl_xor_sync(0xffffffffu, p[1], off);
                p[2] += __shfl_xor_sync(0xffffffffu, p[2], off);
                p[3] += __shfl_xor_sync(0xffffffffu, p[3], off);
            }
            if (tig == 0) {
                atomicAdd(&sAttn[m_base + g],      p[0]);
                atomicAdd(&sAttn[m_base + g + 8],  p[1]);
                atomicAdd(&sAttn[m_base + g + 16], p[2]);
                atomicAdd(&sAttn[m_base + g + 24], p[3]);
            }
        }
        __syncthreads();
        // --- mask + ba3 ---
        if (tid < 128) {
            float a = sAttn[tid] + ba3v;
            sAttn[tid] = sE[tid * 6 + 5] * a;
        }
        __syncthreads();
        // --- ctx += attn . vproj ---
        {
            int d = tid & 63, grp = tid >> 6;          // grp 0..7, 16 rows each
            float partial = 0.f;
            const float* vp = d_vproj + (b * NN + k0 + grp * 16) * FF + d;
#pragma unroll 8
            for (int m = 0; m < 16; ++m) partial += sAttn[grp * 16 + m] * vp[m * FF];
            sCtxAcc[grp * 64 + d] += partial;
        }
        __syncthreads();
    }

    // --- reduce + LayerNorm1 ---
    if (tid < 64) {
        float s = 0.f;
#pragma unroll
        for (int gg = 0; gg < 8; ++gg) s += sCtxAcc[gg * 64 + tid];
        sCtxRow[tid] = s;
    }
    __syncthreads();
    if (tid < 32) {
        float s = sCtxRow[tid] + sCtxRow[tid + 32];
#pragma unroll
        for (int off = 16; off > 0; off >>= 1) s += __shfl_xor_sync(0xffffffffu, s, off);
        if (tid == 0) sRed[0] = s * (1.f / 64.f);
    }
    __syncthreads();
    if (tid < 32) {
        float mu = sRed[0];
        float d0 = sCtxRow[tid] - mu, d1 = sCtxRow[tid + 32] - mu;
        float s = d0 * d0 + d1 * d1;
#pragma unroll
        for (int off = 16; off > 0; off >>= 1) s += __shfl_xor_sync(0xffffffffu, s, off);
        if (tid == 0) sRed[1] = rsqrtf(s * (1.f / 64.f) + LN_EPS);
    }
    __syncthreads();
    if (tid < 64) {
        float mu = sRed[0], rs = sRed[1];
        float o = (sCtxRow[tid] - mu) * rs * ln1_s[tid] + ln1_b[tid];
        out[rowq * FF + tid] = o;
        sCtxRow[tid] = o;
    }
    __syncthreads();
    // --- gate MLP + masked max-pool (q < vlen guaranteed) ---
    if (tid < 256) {
        float hg = bg1[tid];
#pragma unroll 8
        for (int f = 0; f < FF; ++f) hg += sCtxRow[f] * Wg1[f * CC + tid];
        sHg[tid] = gelu_f(hg);
    }
    __syncthreads();
    if (tid < 64) {
        float gsum = bg2[tid];
#pragma unroll 8
        for (int c2 = 0; c2 < CC; ++c2) gsum += sHg[c2] * Wg2[c2 * FF + tid];
        float val = gsum * sCtxRow[tid];
        atomicMaxF(&d_pool[b * FF + tid], val);
    }
}

// ---------------- vnode: LN2 over pooled ----------------
__global__ void k_vnode(const float* __restrict__ ln2_s, const float* __restrict__ ln2_b,
                        float* __restrict__ out) {
    int t = threadIdx.x;           // 0..127
    int b = t >> 6, d = t & 63;
    __shared__ float sp[128], sMu[2], sRs[2];
    float x = d_pool[t];
    sp[t] = x;
    __syncthreads();
    if (t < 2) {
        float mu = 0.f;
        for (int i = 0; i < 64; ++i) mu += sp[t * 64 + i];
        mu *= (1.f / 64.f);
        float v = 0.f;
        for (int i = 0; i < 64; ++i) { float dd = sp[t * 64 + i] - mu; v += dd * dd; }
        v *= (1.f / 64.f);
        sMu[t] = mu;
        sRs[t] = rsqrtf(v + LN_EPS);
    }
    __syncthreads();
    out[BB * NN * FF + t] = (x - sMu[b]) * sRs[b] * ln2_s[d] + ln2_b[d];
}

// ---------------- launch ----------------
extern "C" void kernel_launch(void* const* d_in, const int* in_sizes, int n_in,
                              void* d_out, int out_size) {
    (void)in_sizes; (void)n_in; (void)out_size;
    const float* qs    = (const float*)d_in[0];
    const float* ks    = (const float*)d_in[1];
    const float* vs    = (const float*)d_in[2];
    const float* qs_s  = (const float*)d_in[3];
    const float* ks_s  = (const float*)d_in[4];
    const float* qs_t  = (const float*)d_in[5];
    const float* ks_t  = (const float*)d_in[6];
    const int*   vl    = (const int*)d_in[7];
    const float* Wv    = (const float*)d_in[8];
    const float* bv    = (const float*)d_in[9];
    const float* Wa1   = (const float*)d_in[10];
    const float* ba1   = (const float*)d_in[11];
    const float* Wa2   = (const float*)d_in[12];
    const float* ba2   = (const float*)d_in[13];
    const float* Wa3   = (const float*)d_in[14];
    const float* ba3   = (const float*)d_in[15];
    const float* Wg1   = (const float*)d_in[16];
    const float* bg1   = (const float*)d_in[17];
    const float* Wg2   = (const float*)d_in[18];
    const float* bg2   = (const float*)d_in[19];
    const float* ln1_s = (const float*)d_in[20];
    const float* ln1_b = (const float*)d_in[21];
    const float* ln2_s = (const float*)d_in[22];
    const float* ln2_b = (const float*)d_in[23];
    float* out = (float*)d_out;

    cudaFuncSetAttribute(k_main, cudaFuncAttributeMaxDynamicSharedMemorySize, SMEM_BYTES);

    k_prep<<<BB * NN + 64, 256>>>(qs, ks, vs, Wa1, ba1, Wv, bv, Wa2);
    k_main<<<BB * NN, 512, SMEM_BYTES>>>(qs_s, ks_s, qs_t, ks_t, vl,
                                         Wa1, ba2, Wa3, ba3, ln1_s, ln1_b,
                                         Wg1, bg1, Wg2, bg2, out);
    k_vnode<<<1, 128>>>(ln2_s, ln2_b, out);
}

// round 8
// speedup vs baseline: 1.5167x; 1.0305x over previous
#include <cuda_runtime.h>
#include <cuda_fp16.h>

#define BB 2
#define NN 512
#define FF 64
#define CC 256
#define LN_EPS 1e-6f
#define SUB 64                 // k-rows per subchunk
#define NSUB 8                 // 512 / 64

// ---------------- device scratch (static, no allocation) ----------------
__device__ float  d_Aq[BB * NN * CC];            // qs @ Wa1[0:64] + ba1
__device__ float  d_Ak[BB * NN * CC];            // ks @ Wa1[64:128]
__device__ float  d_vproj[BB * NN * FF];         // vs @ Wv + bv
__device__ __align__(16) __half d_Wa2t[CC * CC]; // Wa2 transposed [n][k], fp16
__device__ float  d_pool[BB * FF];               // max-pool accumulator

// ---------------- helpers ----------------
__device__ __forceinline__ float gelu_f(float x) {
    float z = 0.7978845608028654f * x * fmaf(0.044715f, x * x, 1.0f);
    float t;
    asm("tanh.approx.f32 %0, %1;" : "=f"(t) : "f"(z));
    float hx = 0.5f * x;
    return fmaf(hx, t, hx);
}

__device__ __forceinline__ void mma16816(float d[4], const unsigned a[4], const unsigned b0, const unsigned b1) {
    asm volatile(
        "mma.sync.aligned.m16n8k16.row.col.f32.f16.f16.f32 "
        "{%0,%1,%2,%3}, {%4,%5,%6,%7}, {%8,%9}, {%0,%1,%2,%3};\n"
        : "+f"(d[0]), "+f"(d[1]), "+f"(d[2]), "+f"(d[3])
        : "r"(a[0]), "r"(a[1]), "r"(a[2]), "r"(a[3]), "r"(b0), "r"(b1));
}

__device__ __forceinline__ void ldsm_x4(unsigned r[4], const __half* p) {
    unsigned addr = (unsigned)__cvta_generic_to_shared(p);
    asm volatile("ldmatrix.sync.aligned.m8n8.x4.shared.b16 {%0,%1,%2,%3}, [%4];"
                 : "=r"(r[0]), "=r"(r[1]), "=r"(r[2]), "=r"(r[3]) : "r"(addr));
}

__device__ __forceinline__ void bar_sync(int id, int cnt) {
    asm volatile("bar.sync %0, %1;" :: "r"(id), "r"(cnt) : "memory");
}
__device__ __forceinline__ void bar_arrive(int id, int cnt) {
    asm volatile("bar.arrive %0, %1;" :: "r"(id), "r"(cnt) : "memory");
}

__device__ __forceinline__ void atomicMaxF(float* addr, float v) {
    if (v >= 0.f) atomicMax((int*)addr, __float_as_int(v));
    else          atomicMin((unsigned int*)addr, __float_as_uint(v));
}

// ---------------- prep: Aq/Ak/vproj + Wa2 transpose-to-half + pool init ----------------
__global__ void k_prep(const float* __restrict__ qs, const float* __restrict__ ks,
                       const float* __restrict__ vs, const float* __restrict__ Wa1,
                       const float* __restrict__ ba1, const float* __restrict__ Wv,
                       const float* __restrict__ bv, const float* __restrict__ Wa2) {
    int tid = threadIdx.x;
    if (blockIdx.x < BB * NN) {
        __shared__ float sq[FF], sk[FF], sv[FF];
        int row = blockIdx.x;
        if (tid < FF) {
            sq[tid] = qs[row * FF + tid];
            sk[tid] = ks[row * FF + tid];
            sv[tid] = vs[row * FF + tid];
        }
        __syncthreads();
        float aq = ba1[tid], ak = 0.f;
#pragma unroll 8
        for (int f = 0; f < FF; ++f) {
            aq += sq[f] * Wa1[f * CC + tid];
            ak += sk[f] * Wa1[(FF + f) * CC + tid];
        }
        d_Aq[row * CC + tid] = aq;
        d_Ak[row * CC + tid] = ak;
        if (tid < FF) {
            float vp = bv[tid];
#pragma unroll 8
            for (int f = 0; f < FF; ++f) vp += sv[f] * Wv[f * FF + tid];
            d_vproj[row * FF + tid] = vp;
        }
    } else {
        int blk = blockIdx.x - BB * NN;      // 0..63
        for (int idx = blk * 256 + tid; idx < CC * CC; idx += 64 * 256) {
            int kk = idx >> 8, n = idx & 255;
            d_Wa2t[n * CC + kk] = __float2half(Wa2[idx]);
        }
        if (blk == 0 && tid < BB * FF) d_pool[tid] = __int_as_float(0xff800000); // -inf
    }
}

// ---------------- main fused kernel: one CTA per (b, q), 512 threads ----------------
// Warp specialization: warps 0-7 produce h1 tiles (FMA/MUFU), warps 8-15
// consume them (HMMA GEMM + epilogue + attn.vproj), double-buffered over
// 64-row subchunks so the tensor pipe overlaps the scalar pipes.
#define PITCH 264
#define SMEM_BYTES ((256 + 2 * SUB) * PITCH * 2 + 3522 * 4)

// named barrier ids: 1,2 = full[0/1]; 3,4 = empty[0/1]; 5 = consumers; 6 = producers
__global__ void __launch_bounds__(512, 1)
k_main(const float* __restrict__ qs_s, const float* __restrict__ ks_s,
       const float* __restrict__ qs_t, const float* __restrict__ ks_t,
       const int* __restrict__ valid_lens,
       const float* __restrict__ Wa1, const float* __restrict__ ba2,
       const float* __restrict__ Wa3, const float* __restrict__ ba3,
       const float* __restrict__ ln1_s, const float* __restrict__ ln1_b,
       const float* __restrict__ Wg1, const float* __restrict__ bg1,
       const float* __restrict__ Wg2, const float* __restrict__ bg2,
       float* __restrict__ out) {
    extern __shared__ char smem_raw[];
    __half* sWb = (__half*)smem_raw;        // [256][PITCH]  Wa2^T padded
    __half* sH  = sWb + 256 * PITCH;        // [2][SUB][PITCH]  h1 ping-pong (fp16)
    float* fbse   = (float*)(sH + 2 * SUB * PITCH);
    float* sAq    = fbse;                   // 256
    float* sWe    = sAq + 256;              // 5*256 (Wa1 rows 128..132)
    float* sBa2   = sWe + 1280;             // 256
    float* sWa3   = sBa2 + 256;             // 256
    float* sE     = sWa3 + 256;             // [2][SUB][6]
    float* sAttn  = sE + 2 * SUB * 6;       // [2][SUB]
    float* sCtxAcc= sAttn + 2 * SUB;        // [4][64]
    float* sCtxRow= sCtxAcc + 256;          // 64
    float* sHg    = sCtxRow + 64;           // 256
    float* sRed   = sHg + 256;              // 2

    const int tid  = threadIdx.x;
    const int b    = blockIdx.x >> 9;
    const int q    = blockIdx.x & 511;
    const int rowq = b * NN + q;

    const int vlen = valid_lens[b];
    // mask = (q < vlen) && (t_diff > 0): validity applies to the QUERY axis.
    if (q >= vlen) {
        if (tid < FF) out[rowq * FF + tid] = ln1_b[tid];
        return;
    }

    // ---- prologue: constants into SMEM (all 512 threads) ----
    {
        const uint4* src = (const uint4*)d_Wa2t;
        for (int i = tid; i < 256 * 32; i += 512) {
            int n = i >> 5, j = i & 31;
            *(uint4*)(sWb + n * PITCH + j * 8) = src[i];
        }
    }
    if (tid < 256) {
        sAq[tid]  = d_Aq[rowq * CC + tid];
        sBa2[tid] = ba2[tid];
        sWa3[tid] = Wa3[tid];
        sCtxAcc[tid] = 0.f;
    }
    for (int i = tid; i < 5 * 256; i += 512) sWe[i] = Wa1[128 * CC + i];
    const float qsx = qs_s[rowq * 2 + 0], qsy = qs_s[rowq * 2 + 1];
    const float qt  = qs_t[rowq];
    const float ba3v = ba3[0];
    __syncthreads();

    const int lane = tid & 31, warp = tid >> 5;

    if (warp < 8) {
        // ================= PRODUCER: features + h1 ==================
        const int cp = tid & 127;            // column pair 0..127
        const int c  = cp * 2;
        const int m0 = tid >> 7;             // 0..1
        const float aq0 = sAq[c], aq1 = sAq[c + 1];
        const float w00 = sWe[c],        w01 = sWe[c + 1];
        const float w10 = sWe[256 + c],  w11 = sWe[257 + c];
        const float w20 = sWe[512 + c],  w21 = sWe[513 + c];
        const float w30 = sWe[768 + c],  w31 = sWe[769 + c];
        const float w40 = sWe[1024 + c], w41 = sWe[1025 + c];

        for (int s = 0; s < NSUB; ++s) {
            const int p = s & 1;
            const int k0 = s * SUB;
            if (s >= 2) bar_sync(3 + p, 512);          // wait buffer empty
            if (tid < SUB) {
                int krow = b * NN + k0 + tid;
                float dx = qsx - ks_s[krow * 2 + 0];
                float dy = qsy - ks_s[krow * 2 + 1];
                float dist = sqrtf(dx * dx + dy * dy);
                float td = qt - ks_t[krow];
                float* e = sE + (p * SUB + tid) * 6;
                e[0] = dx; e[1] = dy; e[2] = dist; e[3] = dist * dist;
                e[4] = td; e[5] = (td > 0.f) ? 1.f : 0.f;
                sAttn[p * SUB + tid] = 0.f;
            }
            bar_sync(6, 256);                          // producer internal
            __half* sHp = sH + p * SUB * PITCH;
            const float2* akp = (const float2*)(d_Ak + (b * NN + k0 + m0) * CC) + cp;
#pragma unroll 4
            for (int it = 0; it < SUB / 2; ++it) {
                const int m = m0 + it * 2;
                float2 ak = akp[it * 2 * (CC / 2)];
                const float* e = sE + (p * SUB + m) * 6;
                float e0 = e[0], e1 = e[1], e2 = e[2], e3 = e[3], e4 = e[4];
                float p0 = aq0 + ak.x + e0 * w00 + e1 * w10 + e2 * w20 + e3 * w30 + e4 * w40;
                float p1 = aq1 + ak.y + e0 * w01 + e1 * w11 + e2 * w21 + e3 * w31 + e4 * w41;
                *(__half2*)(sHp + m * PITCH + c) = __floats2half2_rn(gelu_f(p0), gelu_f(p1));
            }
            __threadfence_block();
            bar_arrive(1 + p, 512);                    // publish full
        }
    } else {
        // ================= CONSUMER: GEMM + epilogue + vproj =========
        const int tc = tid - 256;
        const int cw = warp - 8;
        const int g = lane >> 2, tig = lane & 3;
        const int wm2 = cw >> 2, wn = cw & 3;          // 2x4 warp grid
        const int m_base = wm2 * 32;                   // 32 rows per warp (of 64)
        const int n_base = wn * 64;                    // 64 cols per warp
        const int lrow = lane & 15;
        const int lcol = (lane >> 4) << 3;
        const int d_    = tc & 63, grp = tc >> 6;      // vproj mapping

        for (int s = 0; s < NSUB; ++s) {
            const int p = s & 1;
            const int k0 = s * SUB;
            bar_sync(1 + p, 512);                      // wait buffer full
            const __half* sHp = sH + p * SUB * PITCH;

            float acc[2][8][4];
#pragma unroll
            for (int mt = 0; mt < 2; ++mt)
#pragma unroll
                for (int nt = 0; nt < 8; ++nt)
#pragma unroll
                    for (int r = 0; r < 4; ++r) acc[mt][nt][r] = 0.f;

            const __half* pa0 = sHp + (m_base + lrow) * PITCH + lcol;
            const __half* pb0 = sWb + (n_base + lrow) * PITCH + lcol;
#pragma unroll 2
            for (int kk = 0; kk < 256; kk += 16) {
                unsigned afr[2][4];
                ldsm_x4(afr[0], pa0 + kk);
                ldsm_x4(afr[1], pa0 + 16 * PITCH + kk);
#pragma unroll
                for (int nb = 0; nb < 4; ++nb) {
                    unsigned bfr[4];
                    ldsm_x4(bfr, pb0 + nb * 16 * PITCH + kk);
#pragma unroll
                    for (int mt = 0; mt < 2; ++mt) {
                        mma16816(acc[mt][nb * 2 + 0], afr[mt], bfr[0], bfr[2]);
                        mma16816(acc[mt][nb * 2 + 1], afr[mt], bfr[1], bfr[3]);
                    }
                }
            }
            // epilogue: h2 = gelu(acc + ba2); partial attn = h2 . Wa3
            float pr[4] = {0.f, 0.f, 0.f, 0.f};
#pragma unroll
            for (int nt = 0; nt < 8; ++nt) {
                int col = n_base + nt * 8 + 2 * tig;
                float bb0 = sBa2[col], bb1 = sBa2[col + 1];
                float w0 = sWa3[col], w1 = sWa3[col + 1];
#pragma unroll
                for (int mt = 0; mt < 2; ++mt) {
                    pr[mt * 2 + 0] += gelu_f(acc[mt][nt][0] + bb0) * w0
                                    + gelu_f(acc[mt][nt][1] + bb1) * w1;
                    pr[mt * 2 + 1] += gelu_f(acc[mt][nt][2] + bb0) * w0
                                    + gelu_f(acc[mt][nt][3] + bb1) * w1;
                }
            }
#pragma unroll
            for (int off = 1; off < 4; off <<= 1) {
                pr[0] += __shfl_xor_sync(0xffffffffu, pr[0], off);
                pr[1] += __shfl_xor_sync(0xffffffffu, pr[1], off);
                pr[2] += __shfl_xor_sync(0xffffffffu, pr[2], off);
                pr[3] += __shfl_xor_sync(0xffffffffu, pr[3], off);
            }
            if (tig == 0) {
                atomicAdd(&sAttn[p * SUB + m_base + g],      pr[0]);
                atomicAdd(&sAttn[p * SUB + m_base + g + 8],  pr[1]);
                atomicAdd(&sAttn[p * SUB + m_base + g + 16], pr[2]);
                atomicAdd(&sAttn[p * SUB + m_base + g + 24], pr[3]);
            }
            bar_sync(5, 256);                          // consumer internal
            // ctx += masked(attn) . vproj  (mask applied inline)
            {
                float partial = 0.f;
                const float* vp = d_vproj + (b * NN + k0 + grp * 16) * FF + d_;
#pragma unroll 8
                for (int m = 0; m < 16; ++m) {
                    int row = grp * 16 + m;
                    float a = (sAttn[p * SUB + row] + ba3v) * sE[(p * SUB + row) * 6 + 5];
                    partial += a * vp[m * FF];
                }
                sCtxAcc[grp * 64 + d_] += partial;
            }
            bar_arrive(3 + p, 512);                    // release buffer
        }
    }
    __syncthreads();

    // --- reduce + LayerNorm1 ---
    if (tid < 64) {
        float s = sCtxAcc[tid] + sCtxAcc[64 + tid] + sCtxAcc[128 + tid] + sCtxAcc[192 + tid];
        sCtxRow[tid] = s;
    }
    __syncthreads();
    if (tid < 32) {
        float s = sCtxRow[tid] + sCtxRow[tid + 32];
#pragma unroll
        for (int off = 16; off > 0; off >>= 1) s += __shfl_xor_sync(0xffffffffu, s, off);
        if (tid == 0) sRed[0] = s * (1.f / 64.f);
    }
    __syncthreads();
    if (tid < 32) {
        float mu = sRed[0];
        float d0 = sCtxRow[tid] - mu, d1 = sCtxRow[tid + 32] - mu;
        float s = d0 * d0 + d1 * d1;
#pragma unroll
        for (int off = 16; off > 0; off >>= 1) s += __shfl_xor_sync(0xffffffffu, s, off);
        if (tid == 0) sRed[1] = rsqrtf(s * (1.f / 64.f) + LN_EPS);
    }
    __syncthreads();
    if (tid < 64) {
        float mu = sRed[0], rs = sRed[1];
        float o = (sCtxRow[tid] - mu) * rs * ln1_s[tid] + ln1_b[tid];
        out[rowq * FF + tid] = o;
        sCtxRow[tid] = o;
    }
    __syncthreads();
    // --- gate MLP + masked max-pool (q < vlen guaranteed) ---
    if (tid < 256) {
        float hg = bg1[tid];
#pragma unroll 8
        for (int f = 0; f < FF; ++f) hg += sCtxRow[f] * Wg1[f * CC + tid];
        sHg[tid] = gelu_f(hg);
    }
    __syncthreads();
    if (tid < 64) {
        float gsum = bg2[tid];
#pragma unroll 8
        for (int c2 = 0; c2 < CC; ++c2) gsum += sHg[c2] * Wg2[c2 * FF + tid];
        float val = gsum * sCtxRow[tid];
        atomicMaxF(&d_pool[b * FF + tid], val);
    }
}

// ---------------- vnode: LN2 over pooled ----------------
__global__ void k_vnode(const float* __restrict__ ln2_s, const float* __restrict__ ln2_b,
                        float* __restrict__ out) {
    int t = threadIdx.x;           // 0..127
    int b = t >> 6, d = t & 63;
    __shared__ float sp[128], sMu[2], sRs[2];
    float x = d_pool[t];
    sp[t] = x;
    __syncthreads();
    if (t < 2) {
        float mu = 0.f;
        for (int i = 0; i < 64; ++i) mu += sp[t * 64 + i];
        mu *= (1.f / 64.f);
        float v = 0.f;
        for (int i = 0; i < 64; ++i) { float dd = sp[t * 64 + i] - mu; v += dd * dd; }
        v *= (1.f / 64.f);
        sMu[t] = mu;
        sRs[t] = rsqrtf(v + LN_EPS);
    }
    __syncthreads();
    out[BB * NN * FF + t] = (x - sMu[b]) * sRs[b] * ln2_s[d] + ln2_b[d];
}

// ---------------- launch ----------------
extern "C" void kernel_launch(void* const* d_in, const int* in_sizes, int n_in,
                              void* d_out, int out_size) {
    (void)in_sizes; (void)n_in; (void)out_size;
    const float* qs    = (const float*)d_in[0];
    const float* ks    = (const float*)d_in[1];
    const float* vs    = (const float*)d_in[2];
    const float* qs_s  = (const float*)d_in[3];
    const float* ks_s  = (const float*)d_in[4];
    const float* qs_t  = (const float*)d_in[5];
    const float* ks_t  = (const float*)d_in[6];
    const int*   vl    = (const int*)d_in[7];
    const float* Wv    = (const float*)d_in[8];
    const float* bv    = (const float*)d_in[9];
    const float* Wa1   = (const float*)d_in[10];
    const float* ba1   = (const float*)d_in[11];
    const float* Wa2   = (const float*)d_in[12];
    const float* ba2   = (const float*)d_in[13];
    const float* Wa3   = (const float*)d_in[14];
    const float* ba3   = (const float*)d_in[15];
    const float* Wg1   = (const float*)d_in[16];
    const float* bg1   = (const float*)d_in[17];
    const float* Wg2   = (const float*)d_in[18];
    const float* bg2   = (const float*)d_in[19];
    const float* ln1_s = (const float*)d_in[20];
    const float* ln1_b = (const float*)d_in[21];
    const float* ln2_s = (const float*)d_in[22];
    const float* ln2_b = (const float*)d_in[23];
    float* out = (float*)d_out;

    cudaFuncSetAttribute(k_main, cudaFuncAttributeMaxDynamicSharedMemorySize, SMEM_BYTES);

    k_prep<<<BB * NN + 64, 256>>>(qs, ks, vs, Wa1, ba1, Wv, bv, Wa2);
    k_main<<<BB * NN, 512, SMEM_BYTES>>>(qs_s, ks_s, qs_t, ks_t, vl,
                                         Wa1, ba2, Wa3, ba3, ln1_s, ln1_b,
                                         Wg1, bg1, Wg2, bg2, out);
    k_vnode<<<1, 128>>>(ln2_s, ln2_b, out);
}